// round 12
// baseline (speedup 1.0000x reference)
#include <cuda_runtime.h>
#include <math.h>
#include <stdint.h>

#define NT 4096      // tokens
#define NDM 2048     // d_model
#define NF 8192      // d_ff
#define NE 8         // experts

#define BM 128
#define BN 256
#define BK 32

// 16B fragment words; tiles of 32 words padded for bank-conflict-free STS
#define A_TILE_W 33                       // 16x8 A mtile: 32 words + 1 pad
#define B_TILE_W 36                       // 8x16 B npair-tile: 32 words + 4 pad
#define A_STAGE_B (32 * A_TILE_W * 16)    // 16896 B
#define B_STAGE_B (64 * B_TILE_W * 16)    // 36864 B
#define STAGE_B   (A_STAGE_B + B_STAGE_B) // 53760 B
#define SMEM_BYTES (2 * STAGE_B + 640)    // ~105.6 KB

// -------- device scratch --------
__device__ int   g_counts[NE];
__device__ int   g_tok[NE][NT];
__device__ float g_w[NT];
__device__ float g_h[(size_t)NT * NF];

__device__ __forceinline__ float gelu_exact(float v) {
    return 0.5f * v * (1.0f + erff(v * 0.70710678118654752440f));
}

__global__ void reset_kernel() {
    if (threadIdx.x < NE) g_counts[threadIdx.x] = 0;
}

__global__ void router_kernel(const float* __restrict__ x,
                              const float* __restrict__ Wr) {
    const int t = blockIdx.x;
    const float* xr = x + (size_t)t * NDM;
    float acc[NE];
#pragma unroll
    for (int e = 0; e < NE; e++) acc[e] = 0.f;
    for (int d = threadIdx.x; d < NDM; d += 256) {
        const float xv = xr[d];
#pragma unroll
        for (int e = 0; e < NE; e++) acc[e] += xv * Wr[e * NDM + d];
    }
#pragma unroll
    for (int off = 16; off > 0; off >>= 1) {
#pragma unroll
        for (int e = 0; e < NE; e++)
            acc[e] += __shfl_down_sync(0xffffffffu, acc[e], off);
    }
    __shared__ float red[8][NE];
    const int warp = threadIdx.x >> 5;
    const int lane = threadIdx.x & 31;
    if (lane == 0) {
#pragma unroll
        for (int e = 0; e < NE; e++) red[warp][e] = acc[e];
    }
    __syncthreads();
    if (threadIdx.x == 0) {
        float l[NE];
#pragma unroll
        for (int e = 0; e < NE; e++) {
            float s = 0.f;
#pragma unroll
            for (int w = 0; w < 8; w++) s += red[w][e];
            l[e] = s;
        }
        float m = l[0]; int bi = 0;
#pragma unroll
        for (int e = 1; e < NE; e++) {
            if (l[e] > m) { m = l[e]; bi = e; }  // first-max = jnp.argmax
        }
        float s = 0.f;
#pragma unroll
        for (int e = 0; e < NE; e++) s += expf(l[e] - m);
        g_w[t] = 1.0f / s;
        const int slot = atomicAdd(&g_counts[bi], 1);
        g_tok[bi][slot] = t;
    }
}

// -------- asm helpers --------
static __device__ __forceinline__ uint32_t f2tf32(float f) {
    uint32_t u; asm("cvt.rna.tf32.f32 %0, %1;" : "=r"(u) : "f"(f)); return u;
}
static __device__ __forceinline__ void sts128(uint32_t a, uint32_t x, uint32_t y,
                                              uint32_t z, uint32_t w) {
    asm volatile("st.shared.v4.b32 [%0], {%1,%2,%3,%4};"
                 :: "r"(a), "r"(x), "r"(y), "r"(z), "r"(w));
}
static __device__ __forceinline__ void lds128(uint32_t a, uint32_t* r) {
    asm volatile("ld.shared.v4.b32 {%0,%1,%2,%3}, [%4];"
                 : "=r"(r[0]), "=r"(r[1]), "=r"(r[2]), "=r"(r[3]) : "r"(a));
}
static __device__ __forceinline__ void mma_tf32(float* c, const uint32_t* a, const uint32_t* b) {
    asm volatile(
        "mma.sync.aligned.m16n8k8.row.col.f32.tf32.tf32.f32 "
        "{%0,%1,%2,%3}, {%4,%5,%6,%7}, {%8,%9}, {%0,%1,%2,%3};"
        : "+f"(c[0]), "+f"(c[1]), "+f"(c[2]), "+f"(c[3])
        : "r"(a[0]), "r"(a[1]), "r"(a[2]), "r"(a[3]), "r"(b[0]), "r"(b[1]));
}

// -------- grouped TF32 GEMM, fragment-ordered smem, 64x64 warp tiles --------
// MMA(t, buf s) interleaved with STS(t+1, buf 1-s); single barrier per k-tile.
template <bool F1>
__global__ __launch_bounds__(256, 1)
void moe_mma(const float* __restrict__ Asrc,
             const float* __restrict__ W,
             float* __restrict__ Out) {
    constexpr int KD = F1 ? NDM : NF;
    constexpr int ND = F1 ? NF : NDM;
    constexpr int NK = KD / BK;

    const int e   = blockIdx.z;
    const int cnt = g_counts[e];
    const int m0  = blockIdx.y * BM;
    if (m0 >= cnt) return;
    const int n0  = blockIdx.x * BN;

    extern __shared__ float smem[];
    int* toks = (int*)((char*)smem + 2 * STAGE_B);
    const uint32_t sbase = (uint32_t)__cvta_generic_to_shared(smem);

    const int tid  = threadIdx.x;
    const int wid  = tid >> 5;
    const int lane = tid & 31;

    if (tid < BM) {
        const int m = m0 + tid;
        toks[tid] = (m < cnt) ? g_tok[e][m] : -1;
    }
    __syncthreads();

    const float* A = F1 ? Asrc : (const float*)g_h;

    // ---- A loader: thread -> rows (r, r+8), k-range kseg*8..+7
    const int a_ks   = tid & 3;
    const int a_rp   = tid >> 2;
    const int a_rlow = a_rp & 7;
    const int a_mrow = a_rp >> 3;          // 0..7
    const int ar0 = a_mrow * 16 + a_rlow;
    const int atok0 = toks[ar0];
    const int atok1 = toks[ar0 + 8];
    const float* ap0 = A + (atok0 >= 0 ? (size_t)atok0 * KD : 0) + a_ks * 8;
    const float* ap1 = A + (atok1 >= 0 ? (size_t)atok1 * KD : 0) + a_ks * 8;
    const uint32_t a_sts = sbase +
        (uint32_t)(((a_mrow * 4 + a_ks) * A_TILE_W + a_rlow * 4) * 16);

    // ---- B loader: thread -> rows (klo, klo+4), two npair groups (np0, np0+8)
    const int b_kc  = tid & 3;
    const int b_npl = (tid >> 2) & 3;
    const int b_ns  = (tid >> 4) & 1;
    const int b_ksg = (tid >> 5) & 3;
    const int b_nph = (tid >> 7) & 1;
    const int b_np0 = b_nph * 4 + b_npl;   // 0..7 ; second group = +8
    const int b_nb  = b_np0 * 16 + b_ns * 4;
    const int b_klo = b_ksg * 8 + b_kc;
    const float* bp = W + (size_t)e * KD * ND + (size_t)b_klo * ND + (n0 + b_nb);
    const uint32_t b_sts = sbase + A_STAGE_B +
        (uint32_t)(((b_ksg * 16 + b_np0) * B_TILE_W + b_ns * 16 + b_kc) * 16);
    const uint32_t b_sts2 = b_sts + (uint32_t)(8 * B_TILE_W * 16);

    // ---- consumer bases: warp tile 64x64; wm = M half, wn = N quarter
    const int wm = wid & 1;
    const int wn = wid >> 1;
    const uint32_t aLds0 = sbase + (uint32_t)(wm * 16 * A_TILE_W * 16) + lane * 16;
    const uint32_t bLds0 = sbase + A_STAGE_B + (uint32_t)(wn * 4 * B_TILE_W * 16) + lane * 16;

    float4 fa0, fa1, fb0, fb1;             // A prefetch (2 rows x 8k)
    float4 g0, g1, g2, g3, g4, g5, g6, g7; // B prefetch (2 k-rows x 2 n-quads x 2 groups)

#define LOAD(T)                                                            \
    {                                                                      \
        const float* _a0 = ap0 + (size_t)(T) * BK;                         \
        const float* _a1 = ap1 + (size_t)(T) * BK;                         \
        fa0 = *(const float4*)_a0; fa1 = *(const float4*)(_a0 + 4);        \
        fb0 = *(const float4*)_a1; fb1 = *(const float4*)(_a1 + 4);        \
        const float* _b = bp + (size_t)(T) * BK * ND;                      \
        g0 = *(const float4*)_b;                                           \
        g1 = *(const float4*)(_b + 8);                                     \
        g2 = *(const float4*)(_b + 4 * (size_t)ND);                        \
        g3 = *(const float4*)(_b + 4 * (size_t)ND + 8);                    \
        g4 = *(const float4*)(_b + 128);                                   \
        g5 = *(const float4*)(_b + 136);                                   \
        g6 = *(const float4*)(_b + 4 * (size_t)ND + 128);                  \
        g7 = *(const float4*)(_b + 4 * (size_t)ND + 136);                  \
    }

#define STORE_A(OFF)                                                       \
    {                                                                      \
        const uint32_t _as = a_sts + (OFF);                                \
        sts128(_as,      f2tf32(fa0.x), f2tf32(fb0.x), f2tf32(fa1.x), f2tf32(fb1.x)); \
        sts128(_as + 16, f2tf32(fa0.y), f2tf32(fb0.y), f2tf32(fa1.y), f2tf32(fb1.y)); \
        sts128(_as + 32, f2tf32(fa0.z), f2tf32(fb0.z), f2tf32(fa1.z), f2tf32(fb1.z)); \
        sts128(_as + 48, f2tf32(fa0.w), f2tf32(fb0.w), f2tf32(fa1.w), f2tf32(fb1.w)); \
    }

#define STORE_B1(OFF)                                                      \
    {                                                                      \
        const uint32_t _bs = b_sts + (OFF);                                \
        sts128(_bs,       f2tf32(g0.x), f2tf32(g2.x), f2tf32(g1.x), f2tf32(g3.x)); \
        sts128(_bs + 64,  f2tf32(g0.y), f2tf32(g2.y), f2tf32(g1.y), f2tf32(g3.y)); \
        sts128(_bs + 128, f2tf32(g0.z), f2tf32(g2.z), f2tf32(g1.z), f2tf32(g3.z)); \
        sts128(_bs + 192, f2tf32(g0.w), f2tf32(g2.w), f2tf32(g1.w), f2tf32(g3.w)); \
    }

#define STORE_B2(OFF)                                                      \
    {                                                                      \
        const uint32_t _b2 = b_sts2 + (OFF);                               \
        sts128(_b2,       f2tf32(g4.x), f2tf32(g6.x), f2tf32(g5.x), f2tf32(g7.x)); \
        sts128(_b2 + 64,  f2tf32(g4.y), f2tf32(g6.y), f2tf32(g5.y), f2tf32(g7.y)); \
        sts128(_b2 + 128, f2tf32(g4.z), f2tf32(g6.z), f2tf32(g5.z), f2tf32(g7.z)); \
        sts128(_b2 + 192, f2tf32(g4.w), f2tf32(g6.w), f2tf32(g5.w), f2tf32(g7.w)); \
    }

    float acc[4][4][2][4];
#pragma unroll
    for (int i = 0; i < 4; i++)
#pragma unroll
        for (int p = 0; p < 4; p++)
#pragma unroll
            for (int s = 0; s < 2; s++)
#pragma unroll
                for (int q = 0; q < 4; q++) acc[i][p][s][q] = 0.f;

#define MMA_KS(OFF, KS)                                                     \
    {                                                                       \
        uint32_t af[4][4];                                                  \
        _Pragma("unroll") for (int i = 0; i < 4; i++)                       \
            lds128(aLds0 + (OFF) + (i * 4 + (KS)) * (A_TILE_W * 16), af[i]);\
        _Pragma("unroll") for (int p = 0; p < 4; p++) {                     \
            uint32_t bf[4];                                                 \
            lds128(bLds0 + (OFF) + ((KS) * 16 + p) * (B_TILE_W * 16), bf);  \
            _Pragma("unroll") for (int i = 0; i < 4; i++) {                 \
                mma_tf32(acc[i][p][0], af[i], bf);                          \
                mma_tf32(acc[i][p][1], af[i], bf + 2);                      \
            }                                                               \
        }                                                                   \
    }

    LOAD(0)
    STORE_A(0) STORE_B1(0) STORE_B2(0)
    __syncthreads();

#pragma unroll 1
    for (int t = 0; t < NK; t++) {
        const uint32_t off  = (uint32_t)((t & 1) * STAGE_B);
        const uint32_t off2 = (uint32_t)(((t + 1) & 1) * STAGE_B);
        const bool more = (t + 1 < NK);
        if (more) LOAD(t + 1)
        MMA_KS(off, 0)
        MMA_KS(off, 1)
        if (more) STORE_A(off2)
        MMA_KS(off, 2)
        if (more) STORE_B1(off2)
        MMA_KS(off, 3)
        if (more) STORE_B2(off2)
        __syncthreads();
    }

    // ---- epilogue
    const int qr = lane >> 2;
    const int qc = lane & 3;
#pragma unroll
    for (int i = 0; i < 4; i++) {
        const int r0 = wm * 64 + i * 16 + qr;
        const int tok0 = toks[r0];
        const int tok1 = toks[r0 + 8];
#pragma unroll
        for (int p = 0; p < 4; p++)
#pragma unroll
            for (int sub = 0; sub < 2; sub++) {
                const int col = n0 + wn * 64 + p * 16 + sub * 8 + qc * 2;
                const float* c = acc[i][p][sub];
                if (F1) {
                    if (tok0 >= 0) {
                        float2 v = make_float2(gelu_exact(c[0]), gelu_exact(c[1]));
                        *(float2*)(g_h + (size_t)tok0 * NF + col) = v;
                    }
                    if (tok1 >= 0) {
                        float2 v = make_float2(gelu_exact(c[2]), gelu_exact(c[3]));
                        *(float2*)(g_h + (size_t)tok1 * NF + col) = v;
                    }
                } else {
                    if (tok0 >= 0) {
                        const float w0 = g_w[tok0];
                        float2 v = make_float2(c[0] * w0, c[1] * w0);
                        *(float2*)(Out + (size_t)tok0 * NDM + col) = v;
                    }
                    if (tok1 >= 0) {
                        const float w1 = g_w[tok1];
                        float2 v = make_float2(c[2] * w1, c[3] * w1);
                        *(float2*)(Out + (size_t)tok1 * NDM + col) = v;
                    }
                }
            }
    }
#undef LOAD
#undef STORE_A
#undef STORE_B1
#undef STORE_B2
#undef MMA_KS
}

extern "C" void kernel_launch(void* const* d_in, const int* in_sizes, int n_in,
                              void* d_out, int out_size) {
    (void)in_sizes; (void)n_in; (void)out_size;
    const float* x  = (const float*)d_in[0];
    const float* Wr = (const float*)d_in[1];
    const float* W1 = (const float*)d_in[2];
    const float* W2 = (const float*)d_in[3];
    float* out = (float*)d_out;

    cudaFuncSetAttribute(moe_mma<true>,  cudaFuncAttributeMaxDynamicSharedMemorySize, SMEM_BYTES);
    cudaFuncSetAttribute(moe_mma<false>, cudaFuncAttributeMaxDynamicSharedMemorySize, SMEM_BYTES);

    reset_kernel<<<1, 32>>>();
    router_kernel<<<NT, 256>>>(x, Wr);

    dim3 g1(NF / BN, NT / BM, NE);    // (32, 32, 8)
    moe_mma<true><<<g1, 256, SMEM_BYTES>>>(x, W1, out);

    dim3 g2(NDM / BN, NT / BM, NE);   // (8, 32, 8)
    moe_mma<false><<<g2, 256, SMEM_BYTES>>>(x, W2, out);
}